// round 3
// baseline (speedup 1.0000x reference)
#include <cuda_runtime.h>
#include <cuda_bf16.h>

// Problem constants (fixed by the dataset)
#define MAX_N 100000
#define D 128            // D_IN == D_OUT == 128
#define TILE_M 64
#define KCHUNK 32

// Scratch (device globals — no dynamic allocation allowed)
__device__ float g_xw[(size_t)MAX_N * D];   // X @ W, 51.2 MB
__device__ int   g_deg[MAX_N];
__device__ float g_dinv[MAX_N];

// ---------------------------------------------------------------------------
// 1) zero degree counters
__global__ void k_zero_deg(int N) {
    int i = blockIdx.x * blockDim.x + threadIdx.x;
    if (i < N) g_deg[i] = 0;
}

// 2) in-degree (excluding self-loops) via int atomics on destination.
//    edge_index is int32 (JAX x64 disabled -> int64 request silently int32).
__global__ void k_deg(const int* __restrict__ row,
                      const int* __restrict__ col, int E, int N) {
    int e = blockIdx.x * blockDim.x + threadIdx.x;
    if (e < E) {
        int r = row[e];
        int c = col[e];
        if (r != c && (unsigned)c < (unsigned)N) atomicAdd(&g_deg[c], 1);
    }
}

// 3) dinv = rsqrt(deg + 1)   (+1 = appended self-loop; always > 0)
__global__ void k_dinv(int N) {
    int i = blockIdx.x * blockDim.x + threadIdx.x;
    if (i < N) g_dinv[i] = rsqrtf((float)(g_deg[i] + 1));
}

// 4) GEMM: g_xw = X[N,128] @ W[128,128], fp32, static smem only (48KB).
//    Block: 256 threads = 8 warps; 64 rows x 128 cols per block.
//    Xs: full 64x128 tile (32KB). Ws: one 32x128 k-chunk at a time (16KB).
//    Thread (warp w, lane l): rows {w, w+8, ..., w+56}, cols [4l..4l+3].
__global__ void k_gemm(const float* __restrict__ x,
                       const float* __restrict__ w, int N) {
    __shared__ float Xs[TILE_M * D];     // 32 KB
    __shared__ float Ws[KCHUNK * D];     // 16 KB

    int tid = threadIdx.x;
    int lane = tid & 31;
    int warp = tid >> 5;
    int block_row = blockIdx.x * TILE_M;

    // stage X tile: 2048 float4, 8 per thread (zero-pad tail rows)
    const float4* x4  = (const float4*)x;
    float4*       Xs4 = (float4*)Xs;
#pragma unroll
    for (int i = 0; i < 8; i++) {
        int idx = tid + 256 * i;              // idx = local_row*32 + q
        int r = block_row + (idx >> 5);
        float4 v = make_float4(0.f, 0.f, 0.f, 0.f);
        if (r < N) v = x4[(size_t)r * 32 + (idx & 31)];
        Xs4[idx] = v;
    }

    float4 acc[8];
#pragma unroll
    for (int i = 0; i < 8; i++) acc[i] = make_float4(0.f, 0.f, 0.f, 0.f);

    const float4* w4  = (const float4*)w;
    float4*       Ws4 = (float4*)Ws;

#pragma unroll
    for (int kc = 0; kc < D / KCHUNK; kc++) {
        __syncthreads();   // protect Ws reuse (and covers initial Xs fill)
        // stage W chunk: rows [kc*32, kc*32+32) -> 1024 float4, 4 per thread
#pragma unroll
        for (int i = 0; i < 4; i++) {
            int idx = tid + 256 * i;
            Ws4[idx] = w4[kc * KCHUNK * 32 + idx];
        }
        __syncthreads();

#pragma unroll 4
        for (int k = 0; k < KCHUNK; k++) {
            float4 wv = Ws4[k * 32 + lane];   // contiguous 512B: conflict-free
#pragma unroll
            for (int i = 0; i < 8; i++) {
                float xv = Xs[(warp + 8 * i) * D + kc * KCHUNK + k]; // broadcast
                acc[i].x = fmaf(xv, wv.x, acc[i].x);
                acc[i].y = fmaf(xv, wv.y, acc[i].y);
                acc[i].z = fmaf(xv, wv.z, acc[i].z);
                acc[i].w = fmaf(xv, wv.w, acc[i].w);
            }
        }
    }

    float4* xw4 = (float4*)g_xw;
#pragma unroll
    for (int i = 0; i < 8; i++) {
        int r = block_row + warp + 8 * i;
        if (r < N) xw4[(size_t)r * 32 + lane] = acc[i];
    }
}

// 5) init out: out[n] = bias + dinv[n]^2 * xw[n]   (self-loop term)
__global__ void k_self(const float* __restrict__ bias,
                       float* __restrict__ out, int N) {
    int idx = blockIdx.x * blockDim.x + threadIdx.x;   // over N*32 float4s
    if (idx < N * 32) {
        int n = idx >> 5;
        int j = idx & 31;
        float s = g_dinv[n];
        s = s * s;
        float4 v = ((const float4*)g_xw)[idx];
        float4 b = ((const float4*)bias)[j];
        ((float4*)out)[idx] = make_float4(fmaf(s, v.x, b.x),
                                          fmaf(s, v.y, b.y),
                                          fmaf(s, v.z, b.z),
                                          fmaf(s, v.w, b.w));
    }
}

// 6) edge scatter: one warp per edge.
//    gather xw[r] (one float4 per lane), scale by dinv[r]*dinv[c],
//    vector-atomic into out[c] (float4 atomicAdd -> 128-bit RED).
__global__ void k_edges(const int* __restrict__ row,
                        const int* __restrict__ col,
                        float* __restrict__ out, int E, int N) {
    int lane = threadIdx.x & 31;
    int wid  = (blockIdx.x * blockDim.x + threadIdx.x) >> 5;
    if (wid >= E) return;

    int r = __ldg(&row[wid]);
    int c = __ldg(&col[wid]);
    if (r == c) return;                 // original self-loops have weight 0
    if ((unsigned)r >= (unsigned)N || (unsigned)c >= (unsigned)N) return; // safety

    float norm = __ldg(&g_dinv[r]) * __ldg(&g_dinv[c]);
    float4 v = __ldg((const float4*)(g_xw + (size_t)r * D) + lane);
    v.x *= norm; v.y *= norm; v.z *= norm; v.w *= norm;

    float4* dst = (float4*)(out + (size_t)c * D) + lane;
    atomicAdd(dst, v);                  // 128-bit vector reduction
}

extern "C" void kernel_launch(void* const* d_in, const int* in_sizes, int n_in,
                              void* d_out, int out_size) {
    const float* x    = (const float*)d_in[0];
    const int*   ei   = (const int*)d_in[1];     // int32 edge_index [2, E]
    const float* w    = (const float*)d_in[2];
    const float* bias = (const float*)d_in[3];
    float*       out  = (float*)d_out;

    int N = in_sizes[0] / D;
    int E = in_sizes[1] / 2;
    const int* row = ei;
    const int* col = ei + E;

    k_zero_deg<<<(N + 255) / 256, 256>>>(N);
    k_deg<<<(E + 255) / 256, 256>>>(row, col, E, N);
    k_dinv<<<(N + 255) / 256, 256>>>(N);
    k_gemm<<<(N + TILE_M - 1) / TILE_M, 256>>>(x, w, N);
    k_self<<<(N * 32 + 255) / 256, 256>>>(bias, out, N);
    k_edges<<<(E * 32 + 255) / 256, 256>>>(row, col, out, E, N);
}

// round 4
// speedup vs baseline: 1.1218x; 1.1218x over previous
#include <cuda_runtime.h>
#include <cuda_fp16.h>

// Problem constants (fixed by the dataset)
#define MAX_N 100000
#define D 128            // D_IN == D_OUT == 128
#define TILE_M 64
#define KCHUNK 32

// Scratch (device globals — no dynamic allocation allowed)
__device__ __half g_y[(size_t)MAX_N * D];   // dinv[r] * (X@W)[r], fp16, 25.6 MB
__device__ int    g_deg[MAX_N];
__device__ float  g_dinv[MAX_N];

// ---------------------------------------------------------------------------
// 1) zero degree counters
__global__ void k_zero_deg(int N) {
    int i = blockIdx.x * blockDim.x + threadIdx.x;
    if (i < N) g_deg[i] = 0;
}

// 2) in-degree (excluding self-loops) via int atomics on destination (int32 ids)
__global__ void k_deg(const int* __restrict__ row,
                      const int* __restrict__ col, int E, int N) {
    int e = blockIdx.x * blockDim.x + threadIdx.x;
    if (e < E) {
        int r = row[e];
        int c = col[e];
        if (r != c && (unsigned)c < (unsigned)N) atomicAdd(&g_deg[c], 1);
    }
}

// 3) dinv = rsqrt(deg + 1)   (+1 = appended self-loop; always > 0)
__global__ void k_dinv(int N) {
    int i = blockIdx.x * blockDim.x + threadIdx.x;
    if (i < N) g_dinv[i] = rsqrtf((float)(g_deg[i] + 1));
}

// 4) GEMM + fused epilogue:
//    acc = X[N,128] @ W[128,128]
//    g_y[r]  = (half) dinv[r] * acc          (message source, fp16)
//    out[r]  = bias + dinv[r]^2 * acc        (bias + self-loop term, fp32)
//    Block: 256 threads = 8 warps; 64 rows x 128 cols per block; 48KB static smem.
//    Thread (warp w, lane l): rows {w, w+8, ..., w+56}, cols [4l..4l+3].
__global__ void k_gemm(const float* __restrict__ x,
                       const float* __restrict__ w,
                       const float* __restrict__ bias,
                       float* __restrict__ out, int N) {
    __shared__ float Xs[TILE_M * D];     // 32 KB
    __shared__ float Ws[KCHUNK * D];     // 16 KB

    int tid = threadIdx.x;
    int lane = tid & 31;
    int warp = tid >> 5;
    int block_row = blockIdx.x * TILE_M;

    // stage X tile: 2048 float4, 8 per thread (zero-pad tail rows)
    const float4* x4  = (const float4*)x;
    float4*       Xs4 = (float4*)Xs;
#pragma unroll
    for (int i = 0; i < 8; i++) {
        int idx = tid + 256 * i;              // idx = local_row*32 + q
        int r = block_row + (idx >> 5);
        float4 v = make_float4(0.f, 0.f, 0.f, 0.f);
        if (r < N) v = x4[(size_t)r * 32 + (idx & 31)];
        Xs4[idx] = v;
    }

    float4 acc[8];
#pragma unroll
    for (int i = 0; i < 8; i++) acc[i] = make_float4(0.f, 0.f, 0.f, 0.f);

    const float4* w4  = (const float4*)w;
    float4*       Ws4 = (float4*)Ws;

#pragma unroll
    for (int kc = 0; kc < D / KCHUNK; kc++) {
        __syncthreads();   // protect Ws reuse (and covers initial Xs fill)
#pragma unroll
        for (int i = 0; i < 4; i++) {
            int idx = tid + 256 * i;
            Ws4[idx] = w4[kc * KCHUNK * 32 + idx];
        }
        __syncthreads();

#pragma unroll 4
        for (int k = 0; k < KCHUNK; k++) {
            float4 wv = Ws4[k * 32 + lane];   // contiguous 512B: conflict-free
#pragma unroll
            for (int i = 0; i < 8; i++) {
                float xv = Xs[(warp + 8 * i) * D + kc * KCHUNK + k]; // broadcast
                acc[i].x = fmaf(xv, wv.x, acc[i].x);
                acc[i].y = fmaf(xv, wv.y, acc[i].y);
                acc[i].z = fmaf(xv, wv.z, acc[i].z);
                acc[i].w = fmaf(xv, wv.w, acc[i].w);
            }
        }
    }

    // epilogue: y_h = dinv*acc (fp16); out = bias + dinv^2*acc (fp32)
    float4 bv = ((const float4*)bias)[lane];
#pragma unroll
    for (int i = 0; i < 8; i++) {
        int r = block_row + warp + 8 * i;
        if (r >= N) continue;
        float s = g_dinv[r];
        float4 a = acc[i];

        // fp16 message row: 4 halves per lane = 8 bytes
        __half2 h0 = __floats2half2_rn(a.x * s, a.y * s);
        __half2 h1 = __floats2half2_rn(a.z * s, a.w * s);
        float2 packed;  // bit-cast two half2 into 8B store
        packed.x = __uint_as_float(*(unsigned*)&h0);
        packed.y = __uint_as_float(*(unsigned*)&h1);
        ((float2*)(g_y + (size_t)r * D))[lane] = packed;

        float s2 = s * s;
        ((float4*)(out + (size_t)r * D))[lane] =
            make_float4(fmaf(s2, a.x, bv.x), fmaf(s2, a.y, bv.y),
                        fmaf(s2, a.z, bv.z), fmaf(s2, a.w, bv.w));
    }
}

// 5) edge scatter: one warp per edge.
//    gather 8B of fp16 y[r] per lane (256B/row), scale by dinv[c],
//    vector fp32 atomic into out[c] (float4 atomicAdd -> 128-bit RED).
__global__ void k_edges(const int* __restrict__ row,
                        const int* __restrict__ col,
                        float* __restrict__ out, int E, int N) {
    int lane = threadIdx.x & 31;
    int wid  = (blockIdx.x * blockDim.x + threadIdx.x) >> 5;
    if (wid >= E) return;

    int r = __ldg(&row[wid]);
    int c = __ldg(&col[wid]);
    if (r == c) return;                 // original self-loops have weight 0
    if ((unsigned)r >= (unsigned)N || (unsigned)c >= (unsigned)N) return;

    float s = __ldg(&g_dinv[c]);

    // 8B coalesced gather: 4 halves per lane
    float2 raw = __ldg((const float2*)(g_y + (size_t)r * D) + lane);
    unsigned u0 = __float_as_uint(raw.x);
    unsigned u1 = __float_as_uint(raw.y);
    float2 f0 = __half22float2(*(__half2*)&u0);
    float2 f1 = __half22float2(*(__half2*)&u1);

    float4 m = make_float4(f0.x * s, f0.y * s, f1.x * s, f1.y * s);
    float4* dst = (float4*)(out + (size_t)c * D) + lane;
    atomicAdd(dst, m);                  // 128-bit vector reduction
}

extern "C" void kernel_launch(void* const* d_in, const int* in_sizes, int n_in,
                              void* d_out, int out_size) {
    const float* x    = (const float*)d_in[0];
    const int*   ei   = (const int*)d_in[1];     // int32 edge_index [2, E]
    const float* w    = (const float*)d_in[2];
    const float* bias = (const float*)d_in[3];
    float*       out  = (float*)d_out;

    int N = in_sizes[0] / D;
    int E = in_sizes[1] / 2;
    const int* row = ei;
    const int* col = ei + E;

    k_zero_deg<<<(N + 255) / 256, 256>>>(N);
    k_deg<<<(E + 255) / 256, 256>>>(row, col, E, N);
    k_dinv<<<(N + 255) / 256, 256>>>(N);
    k_gemm<<<(N + TILE_M - 1) / TILE_M, 256>>>(x, w, bias, out, N);
    k_edges<<<(E * 32 + 255) / 256, 256>>>(row, col, out, E, N);
}

// round 5
// speedup vs baseline: 1.9744x; 1.7600x over previous
#include <cuda_runtime.h>
#include <cuda_fp16.h>

// Problem constants (fixed by the dataset)
#define MAX_N 100000
#define D 128            // D_IN == D_OUT == 128
#define TILE_M 64
#define KCHUNK 32
#define CAP 64           // padded-CSR bucket capacity per node
#define OVF_MAX 65536    // overflow list capacity (expected use: 0)

// Scratch (device globals — no dynamic allocation allowed)
__device__ __half g_y[(size_t)MAX_N * D];          // dinv[r]*(X@W)[r], fp16
__device__ int    g_cnt[MAX_N];                    // in-degree / fill cursor
__device__ float  g_dinv[MAX_N];
__device__ int    g_bucket[(size_t)MAX_N * CAP];   // source ids, grouped by dest
__device__ int    g_ovf_cnt;
__device__ int2   g_ovf[OVF_MAX];                  // (r, c) spill edges

// ---------------------------------------------------------------------------
// 1) zero cursors + overflow counter
__global__ void k_zero(int N) {
    int i = blockIdx.x * blockDim.x + threadIdx.x;
    if (i < N) g_cnt[i] = 0;
    if (i == 0) g_ovf_cnt = 0;
}

// 2) build padded CSR: cursor atomicAdd gives degree AND slot in one pass
__global__ void k_fill(const int* __restrict__ row,
                       const int* __restrict__ col, int E, int N) {
    int e = blockIdx.x * blockDim.x + threadIdx.x;
    if (e >= E) return;
    int r = row[e];
    int c = col[e];
    if (r == c) return;                                   // self-loop weight 0
    if ((unsigned)r >= (unsigned)N || (unsigned)c >= (unsigned)N) return;
    int slot = atomicAdd(&g_cnt[c], 1);
    if (slot < CAP) {
        g_bucket[(size_t)c * CAP + slot] = r;
    } else {
        int o = atomicAdd(&g_ovf_cnt, 1);
        if (o < OVF_MAX) g_ovf[o] = make_int2(r, c);
    }
}

// 3) dinv = rsqrt(deg + 1)   (+1 = appended self-loop; always > 0)
__global__ void k_dinv(int N) {
    int i = blockIdx.x * blockDim.x + threadIdx.x;
    if (i < N) g_dinv[i] = rsqrtf((float)(g_cnt[i] + 1));
}

// 4) GEMM + fused epilogue:
//    g_y[r] = (half) dinv[r] * (X@W)[r];  out[r] = bias + dinv[r]^2 * (X@W)[r]
__global__ void k_gemm(const float* __restrict__ x,
                       const float* __restrict__ w,
                       const float* __restrict__ bias,
                       float* __restrict__ out, int N) {
    __shared__ float Xs[TILE_M * D];     // 32 KB
    __shared__ float Ws[KCHUNK * D];     // 16 KB

    int tid = threadIdx.x;
    int lane = tid & 31;
    int warp = tid >> 5;
    int block_row = blockIdx.x * TILE_M;

    const float4* x4  = (const float4*)x;
    float4*       Xs4 = (float4*)Xs;
#pragma unroll
    for (int i = 0; i < 8; i++) {
        int idx = tid + 256 * i;              // idx = local_row*32 + q
        int r = block_row + (idx >> 5);
        float4 v = make_float4(0.f, 0.f, 0.f, 0.f);
        if (r < N) v = x4[(size_t)r * 32 + (idx & 31)];
        Xs4[idx] = v;
    }

    float4 acc[8];
#pragma unroll
    for (int i = 0; i < 8; i++) acc[i] = make_float4(0.f, 0.f, 0.f, 0.f);

    const float4* w4  = (const float4*)w;
    float4*       Ws4 = (float4*)Ws;

#pragma unroll
    for (int kc = 0; kc < D / KCHUNK; kc++) {
        __syncthreads();
#pragma unroll
        for (int i = 0; i < 4; i++) {
            int idx = tid + 256 * i;
            Ws4[idx] = w4[kc * KCHUNK * 32 + idx];
        }
        __syncthreads();

#pragma unroll 4
        for (int k = 0; k < KCHUNK; k++) {
            float4 wv = Ws4[k * 32 + lane];
#pragma unroll
            for (int i = 0; i < 8; i++) {
                float xv = Xs[(warp + 8 * i) * D + kc * KCHUNK + k];
                acc[i].x = fmaf(xv, wv.x, acc[i].x);
                acc[i].y = fmaf(xv, wv.y, acc[i].y);
                acc[i].z = fmaf(xv, wv.z, acc[i].z);
                acc[i].w = fmaf(xv, wv.w, acc[i].w);
            }
        }
    }

    float4 bv = ((const float4*)bias)[lane];
#pragma unroll
    for (int i = 0; i < 8; i++) {
        int r = block_row + warp + 8 * i;
        if (r >= N) continue;
        float s = g_dinv[r];
        float4 a = acc[i];

        __half2 h0 = __floats2half2_rn(a.x * s, a.y * s);
        __half2 h1 = __floats2half2_rn(a.z * s, a.w * s);
        float2 packed;
        packed.x = __uint_as_float(*(unsigned*)&h0);
        packed.y = __uint_as_float(*(unsigned*)&h1);
        ((float2*)(g_y + (size_t)r * D))[lane] = packed;

        float s2 = s * s;
        ((float4*)(out + (size_t)r * D))[lane] =
            make_float4(fmaf(s2, a.x, bv.x), fmaf(s2, a.y, bv.y),
                        fmaf(s2, a.z, bv.z), fmaf(s2, a.w, bv.w));
    }
}

// helper: accumulate one fp16 message row into fp32 acc
__device__ __forceinline__ void acc_row(float4& acc, int r, int lane) {
    float2 raw = __ldg((const float2*)(g_y + (size_t)r * D) + lane);
    unsigned u0 = __float_as_uint(raw.x);
    unsigned u1 = __float_as_uint(raw.y);
    float2 f0 = __half22float2(*(__half2*)&u0);
    float2 f1 = __half22float2(*(__half2*)&u1);
    acc.x += f0.x; acc.y += f0.y; acc.z += f1.x; acc.w += f1.y;
}

// 5) per-destination accumulate: one warp per node, register accumulation,
//    single non-atomic RMW of out[c]. No RED traffic.
__global__ void k_acc(float* __restrict__ out, int N) {
    int lane = threadIdx.x & 31;
    int c = (blockIdx.x * blockDim.x + threadIdx.x) >> 5;
    if (c >= N) return;

    int cnt = g_cnt[c];
    if (cnt > CAP) cnt = CAP;           // spill edges handled by k_spill
    if (cnt == 0) return;

    const int* base = g_bucket + (size_t)c * CAP;
    float4 acc = make_float4(0.f, 0.f, 0.f, 0.f);

    for (int b = 0; b < cnt; b += 32) {
        int m = cnt - b; if (m > 32) m = 32;
        int ids = __ldg(base + b + lane);   // coalesced 128B; garbage past m OK
        int j = 0;
        for (; j + 4 <= m; j += 4) {        // 4 independent gathers in flight
            int r0 = __shfl_sync(0xffffffffu, ids, j + 0);
            int r1 = __shfl_sync(0xffffffffu, ids, j + 1);
            int r2 = __shfl_sync(0xffffffffu, ids, j + 2);
            int r3 = __shfl_sync(0xffffffffu, ids, j + 3);
            acc_row(acc, r0, lane);
            acc_row(acc, r1, lane);
            acc_row(acc, r2, lane);
            acc_row(acc, r3, lane);
        }
        for (; j < m; j++) {
            int r0 = __shfl_sync(0xffffffffu, ids, j);
            acc_row(acc, r0, lane);
        }
    }

    float s = g_dinv[c];
    float4* o4 = (float4*)(out + (size_t)c * D) + lane;
    float4 o = *o4;
    o.x = fmaf(s, acc.x, o.x);
    o.y = fmaf(s, acc.y, o.y);
    o.z = fmaf(s, acc.z, o.z);
    o.w = fmaf(s, acc.w, o.w);
    *o4 = o;
}

// 6) spill edges (expected 0): warp per edge, atomic vector RED.
//    Runs AFTER k_acc so it never races the non-atomic RMW above.
__global__ void k_spill(float* __restrict__ out, int N) {
    int lane = threadIdx.x & 31;
    int gw = (blockIdx.x * blockDim.x + threadIdx.x) >> 5;
    int nw = (gridDim.x * blockDim.x) >> 5;
    int ovf = g_ovf_cnt;
    if (ovf > OVF_MAX) ovf = OVF_MAX;
    for (int o = gw; o < ovf; o += nw) {
        int2 e = g_ovf[o];
        float norm = __ldg(&g_dinv[e.y]);   // g_y already has dinv[r]
        float2 raw = __ldg((const float2*)(g_y + (size_t)e.x * D) + lane);
        unsigned u0 = __float_as_uint(raw.x);
        unsigned u1 = __float_as_uint(raw.y);
        float2 f0 = __half22float2(*(__half2*)&u0);
        float2 f1 = __half22float2(*(__half2*)&u1);
        float4 m = make_float4(f0.x * norm, f0.y * norm, f1.x * norm, f1.y * norm);
        atomicAdd((float4*)(out + (size_t)e.y * D) + lane, m);
    }
}

extern "C" void kernel_launch(void* const* d_in, const int* in_sizes, int n_in,
                              void* d_out, int out_size) {
    const float* x    = (const float*)d_in[0];
    const int*   ei   = (const int*)d_in[1];     // int32 edge_index [2, E]
    const float* w    = (const float*)d_in[2];
    const float* bias = (const float*)d_in[3];
    float*       out  = (float*)d_out;

    int N = in_sizes[0] / D;
    int E = in_sizes[1] / 2;
    const int* row = ei;
    const int* col = ei + E;

    k_zero<<<(N + 255) / 256, 256>>>(N);
    k_fill<<<(E + 255) / 256, 256>>>(row, col, E, N);
    k_dinv<<<(N + 255) / 256, 256>>>(N);
    k_gemm<<<(N + TILE_M - 1) / TILE_M, 256>>>(x, w, bias, out, N);
    k_acc<<<(N * 32 + 255) / 256, 256>>>(out, N);
    k_spill<<<64, 256>>>(out, N);
}

// round 6
// speedup vs baseline: 2.0444x; 1.0354x over previous
#include <cuda_runtime.h>
#include <cuda_fp16.h>

// Problem constants (fixed by the dataset)
#define MAX_N 100000
#define D 128            // D_IN == D_OUT == 128
#define TILE_M 64
#define KCHUNK 32
#define CAP 64           // padded-CSR bucket capacity per node
#define OVF_MAX 65536    // overflow list capacity (expected use: 0)

typedef unsigned long long u64;

// Scratch (device globals — no dynamic allocation allowed)
__device__ __half g_y[(size_t)MAX_N * D];          // dinv[r]*(X@W)[r], fp16
__device__ int    g_cnt[MAX_N];                    // in-degree / fill cursor
__device__ int    g_bucket[(size_t)MAX_N * CAP];   // source ids, grouped by dest
__device__ int    g_ovf_cnt;
__device__ int2   g_ovf[OVF_MAX];                  // (r, c) spill edges

// ---------------------------------------------------------------------------
__device__ __forceinline__ u64 pack2(float a, float b) {
    u64 r; asm("mov.b64 %0, {%1, %2};" : "=l"(r) : "f"(a), "f"(b)); return r;
}
__device__ __forceinline__ void unpack2(float& a, float& b, u64 v) {
    asm("mov.b64 {%0, %1}, %2;" : "=f"(a), "=f"(b) : "l"(v));
}
__device__ __forceinline__ void fma2(u64& d, u64 a, u64 b) {
    asm("fma.rn.f32x2 %0, %1, %2, %0;" : "+l"(d) : "l"(a), "l"(b));
}

// 1) zero cursors + overflow counter
__global__ void k_zero(int N) {
    int i = blockIdx.x * blockDim.x + threadIdx.x;
    if (i < N) g_cnt[i] = 0;
    if (i == 0) g_ovf_cnt = 0;
}

// 2) build padded CSR: cursor atomicAdd gives degree AND slot in one pass
__global__ void k_fill(const int* __restrict__ row,
                       const int* __restrict__ col, int E, int N) {
    int e = blockIdx.x * blockDim.x + threadIdx.x;
    if (e >= E) return;
    int r = row[e];
    int c = col[e];
    if (r == c) return;                                   // self-loop weight 0
    if ((unsigned)r >= (unsigned)N || (unsigned)c >= (unsigned)N) return;
    int slot = atomicAdd(&g_cnt[c], 1);
    if (slot < CAP) {
        g_bucket[(size_t)c * CAP + slot] = r;
    } else {
        int o = atomicAdd(&g_ovf_cnt, 1);
        if (o < OVF_MAX) g_ovf[o] = make_int2(r, c);
    }
}

// 3) GEMM (packed f32x2 FMA) + fused epilogue:
//    g_y[r] = (half) dinv[r]*(X@W)[r];  out[r] = bias + dinv[r]^2*(X@W)[r]
//    Block: 256 threads = 8 warps; 64 rows x 128 cols.
//    Thread (warp w, lane l): rows {w+8i}, cols [4l..4l+3] as 2 f32x2 pairs.
__global__ void k_gemm(const float* __restrict__ x,
                       const float* __restrict__ w,
                       const float* __restrict__ bias,
                       float* __restrict__ out, int N) {
    __shared__ float Xs[TILE_M * D];     // 32 KB
    __shared__ float Ws[KCHUNK * D];     // 16 KB

    int tid = threadIdx.x;
    int lane = tid & 31;
    int warp = tid >> 5;
    int block_row = blockIdx.x * TILE_M;

    const float4* x4  = (const float4*)x;
    float4*       Xs4 = (float4*)Xs;
#pragma unroll
    for (int i = 0; i < 8; i++) {
        int idx = tid + 256 * i;              // idx = local_row*32 + q
        int r = block_row + (idx >> 5);
        float4 v = make_float4(0.f, 0.f, 0.f, 0.f);
        if (r < N) v = x4[(size_t)r * 32 + (idx & 31)];
        Xs4[idx] = v;
    }

    u64 acc[8][2];
#pragma unroll
    for (int i = 0; i < 8; i++) { acc[i][0] = 0ull; acc[i][1] = 0ull; } // = {0,0}

    const float4* w4  = (const float4*)w;
    float4*       Ws4 = (float4*)Ws;
    const ulonglong2* Ws2 = (const ulonglong2*)Ws;

    for (int kc = 0; kc < D / KCHUNK; kc++) {
        __syncthreads();   // protect Ws reuse (and covers initial Xs fill)
#pragma unroll
        for (int i = 0; i < 4; i++) {
            int idx = tid + 256 * i;
            Ws4[idx] = w4[kc * KCHUNK * 32 + idx];
        }
        __syncthreads();

#pragma unroll
        for (int k4 = 0; k4 < KCHUNK / 4; k4++) {
            // W pairs for 4 consecutive k: 4x LDS.128 -> 8 f32x2
            ulonglong2 wv0 = Ws2[(k4 * 4 + 0) * 32 + lane];
            ulonglong2 wv1 = Ws2[(k4 * 4 + 1) * 32 + lane];
            ulonglong2 wv2 = Ws2[(k4 * 4 + 2) * 32 + lane];
            ulonglong2 wv3 = Ws2[(k4 * 4 + 3) * 32 + lane];
#pragma unroll
            for (int i = 0; i < 8; i++) {
                const float4 xv =
                    *(const float4*)&Xs[(warp + 8 * i) * D + kc * KCHUNK + k4 * 4];
                u64 xx0 = pack2(xv.x, xv.x);
                u64 xx1 = pack2(xv.y, xv.y);
                u64 xx2 = pack2(xv.z, xv.z);
                u64 xx3 = pack2(xv.w, xv.w);
                fma2(acc[i][0], xx0, wv0.x);  fma2(acc[i][1], xx0, wv0.y);
                fma2(acc[i][0], xx1, wv1.x);  fma2(acc[i][1], xx1, wv1.y);
                fma2(acc[i][0], xx2, wv2.x);  fma2(acc[i][1], xx2, wv2.y);
                fma2(acc[i][0], xx3, wv3.x);  fma2(acc[i][1], xx3, wv3.y);
            }
        }
    }

    float4 bv = ((const float4*)bias)[lane];
#pragma unroll
    for (int i = 0; i < 8; i++) {
        int r = block_row + warp + 8 * i;
        if (r >= N) continue;
        float s = rsqrtf((float)(g_cnt[r] + 1));
        float4 a;
        unpack2(a.x, a.y, acc[i][0]);
        unpack2(a.z, a.w, acc[i][1]);

        __half2 h0 = __floats2half2_rn(a.x * s, a.y * s);
        __half2 h1 = __floats2half2_rn(a.z * s, a.w * s);
        float2 packed;
        packed.x = __uint_as_float(*(unsigned*)&h0);
        packed.y = __uint_as_float(*(unsigned*)&h1);
        ((float2*)(g_y + (size_t)r * D))[lane] = packed;

        float s2 = s * s;
        ((float4*)(out + (size_t)r * D))[lane] =
            make_float4(fmaf(s2, a.x, bv.x), fmaf(s2, a.y, bv.y),
                        fmaf(s2, a.z, bv.z), fmaf(s2, a.w, bv.w));
    }
}

// helper: accumulate one fp16 message row into fp32 acc
__device__ __forceinline__ void acc_row(float4& acc, int r, int lane) {
    float2 raw = __ldg((const float2*)(g_y + (size_t)r * D) + lane);
    unsigned u0 = __float_as_uint(raw.x);
    unsigned u1 = __float_as_uint(raw.y);
    float2 f0 = __half22float2(*(__half2*)&u0);
    float2 f1 = __half22float2(*(__half2*)&u1);
    acc.x += f0.x; acc.y += f0.y; acc.z += f1.x; acc.w += f1.y;
}

// 4) per-destination accumulate: one warp per node, register accumulation,
//    single non-atomic RMW of out[c]. No RED traffic.
__global__ void k_acc(float* __restrict__ out, int N) {
    int lane = threadIdx.x & 31;
    int c = (blockIdx.x * blockDim.x + threadIdx.x) >> 5;
    if (c >= N) return;

    int cnt_full = g_cnt[c];
    int cnt = cnt_full > CAP ? CAP : cnt_full;   // spill handled by k_spill
    if (cnt == 0) return;

    const int* base = g_bucket + (size_t)c * CAP;
    float4 acc = make_float4(0.f, 0.f, 0.f, 0.f);

    for (int b = 0; b < cnt; b += 32) {
        int m = cnt - b; if (m > 32) m = 32;
        int ids = __ldg(base + b + lane);   // coalesced 128B; garbage past m OK
        int j = 0;
        for (; j + 4 <= m; j += 4) {        // 4 independent gathers in flight
            int r0 = __shfl_sync(0xffffffffu, ids, j + 0);
            int r1 = __shfl_sync(0xffffffffu, ids, j + 1);
            int r2 = __shfl_sync(0xffffffffu, ids, j + 2);
            int r3 = __shfl_sync(0xffffffffu, ids, j + 3);
            acc_row(acc, r0, lane);
            acc_row(acc, r1, lane);
            acc_row(acc, r2, lane);
            acc_row(acc, r3, lane);
        }
        for (; j < m; j++) {
            int r0 = __shfl_sync(0xffffffffu, ids, j);
            acc_row(acc, r0, lane);
        }
    }

    float s = rsqrtf((float)(cnt_full + 1));
    float4* o4 = (float4*)(out + (size_t)c * D) + lane;
    float4 o = *o4;
    o.x = fmaf(s, acc.x, o.x);
    o.y = fmaf(s, acc.y, o.y);
    o.z = fmaf(s, acc.z, o.z);
    o.w = fmaf(s, acc.w, o.w);
    *o4 = o;
}

// 5) spill edges (expected 0): warp per edge, atomic vector RED.
//    Runs AFTER k_acc so it never races the non-atomic RMW above.
__global__ void k_spill(float* __restrict__ out, int N) {
    int lane = threadIdx.x & 31;
    int gw = (blockIdx.x * blockDim.x + threadIdx.x) >> 5;
    int nw = (gridDim.x * blockDim.x) >> 5;
    int ovf = g_ovf_cnt;
    if (ovf > OVF_MAX) ovf = OVF_MAX;
    for (int o = gw; o < ovf; o += nw) {
        int2 e = g_ovf[o];
        float norm = rsqrtf((float)(g_cnt[e.y] + 1));  // g_y already has dinv[r]
        float2 raw = __ldg((const float2*)(g_y + (size_t)e.x * D) + lane);
        unsigned u0 = __float_as_uint(raw.x);
        unsigned u1 = __float_as_uint(raw.y);
        float2 f0 = __half22float2(*(__half2*)&u0);
        float2 f1 = __half22float2(*(__half2*)&u1);
        float4 m = make_float4(f0.x * norm, f0.y * norm, f1.x * norm, f1.y * norm);
        atomicAdd((float4*)(out + (size_t)e.y * D) + lane, m);
    }
}

extern "C" void kernel_launch(void* const* d_in, const int* in_sizes, int n_in,
                              void* d_out, int out_size) {
    const float* x    = (const float*)d_in[0];
    const int*   ei   = (const int*)d_in[1];     // int32 edge_index [2, E]
    const float* w    = (const float*)d_in[2];
    const float* bias = (const float*)d_in[3];
    float*       out  = (float*)d_out;

    int N = in_sizes[0] / D;
    int E = in_sizes[1] / 2;
    const int* row = ei;
    const int* col = ei + E;

    k_zero<<<(N + 255) / 256, 256>>>(N);
    k_fill<<<(E + 255) / 256, 256>>>(row, col, E, N);
    k_gemm<<<(N + TILE_M - 1) / TILE_M, 256>>>(x, w, bias, out, N);
    k_acc<<<(N * 32 + 255) / 256, 256>>>(out, N);
    k_spill<<<64, 256>>>(out, N);
}

// round 7
// speedup vs baseline: 2.0537x; 1.0046x over previous
#include <cuda_runtime.h>
#include <cuda_fp16.h>

// Problem constants (fixed by the dataset)
#define MAX_N 100000
#define D 128            // D_IN == D_OUT == 128
#define TILE_M 64
#define KCHUNK 32
#define CAP 64           // padded-CSR bucket capacity per node
#define OVF_MAX 65536    // overflow list capacity (expected use: 0)

typedef unsigned long long u64;

// Scratch (device globals — no dynamic allocation allowed)
__device__ __half g_y[(size_t)MAX_N * D];          // dinv[r]*(X@W)[r], fp16
__device__ int    g_cnt[MAX_N];                    // in-degree / fill cursor
__device__ int    g_bucket[(size_t)MAX_N * CAP];   // source ids, grouped by dest
__device__ int    g_ovf_cnt;
__device__ int2   g_ovf[OVF_MAX];                  // (r, c) spill edges

// ---------------------------------------------------------------------------
__device__ __forceinline__ u64 pack2(float a, float b) {
    u64 r; asm("mov.b64 %0, {%1, %2};" : "=l"(r) : "f"(a), "f"(b)); return r;
}
__device__ __forceinline__ void unpack2(float& a, float& b, u64 v) {
    asm("mov.b64 {%0, %1}, %2;" : "=f"(a), "=f"(b) : "l"(v));
}
__device__ __forceinline__ void fma2(u64& d, u64 a, u64 b) {
    asm("fma.rn.f32x2 %0, %1, %2, %0;" : "+l"(d) : "l"(a), "l"(b));
}

// 1) zero cursors + overflow counter
__global__ void k_zero(int N) {
    int i = blockIdx.x * blockDim.x + threadIdx.x;
    if (i < N) g_cnt[i] = 0;
    if (i == 0) g_ovf_cnt = 0;
}

// 2) build padded CSR: cursor atomicAdd gives degree AND slot in one pass
__global__ void k_fill(const int* __restrict__ row,
                       const int* __restrict__ col, int E, int N) {
    int e = blockIdx.x * blockDim.x + threadIdx.x;
    if (e >= E) return;
    int r = row[e];
    int c = col[e];
    if (r == c) return;                                   // self-loop weight 0
    if ((unsigned)r >= (unsigned)N || (unsigned)c >= (unsigned)N) return;
    int slot = atomicAdd(&g_cnt[c], 1);
    if (slot < CAP) {
        g_bucket[(size_t)c * CAP + slot] = r;
    } else {
        int o = atomicAdd(&g_ovf_cnt, 1);
        if (o < OVF_MAX) g_ovf[o] = make_int2(r, c);
    }
}

// 3) GEMM (packed f32x2 FMA): g_y[r] = (half) dinv[r] * (X@W)[r].
//    No out traffic here — out is produced write-only by k_acc.
//    Block: 256 threads = 8 warps; 64 rows x 128 cols.
__global__ void k_gemm(const float* __restrict__ x,
                       const float* __restrict__ w, int N) {
    __shared__ float Xs[TILE_M * D];     // 32 KB
    __shared__ float Ws[KCHUNK * D];     // 16 KB

    int tid = threadIdx.x;
    int lane = tid & 31;
    int warp = tid >> 5;
    int block_row = blockIdx.x * TILE_M;

    const float4* x4  = (const float4*)x;
    float4*       Xs4 = (float4*)Xs;
#pragma unroll
    for (int i = 0; i < 8; i++) {
        int idx = tid + 256 * i;              // idx = local_row*32 + q
        int r = block_row + (idx >> 5);
        float4 v = make_float4(0.f, 0.f, 0.f, 0.f);
        if (r < N) v = x4[(size_t)r * 32 + (idx & 31)];
        Xs4[idx] = v;
    }

    u64 acc[8][2];
#pragma unroll
    for (int i = 0; i < 8; i++) { acc[i][0] = 0ull; acc[i][1] = 0ull; }

    const float4* w4  = (const float4*)w;
    float4*       Ws4 = (float4*)Ws;
    const ulonglong2* Ws2 = (const ulonglong2*)Ws;

    for (int kc = 0; kc < D / KCHUNK; kc++) {
        __syncthreads();   // protect Ws reuse (and covers initial Xs fill)
#pragma unroll
        for (int i = 0; i < 4; i++) {
            int idx = tid + 256 * i;
            Ws4[idx] = w4[kc * KCHUNK * 32 + idx];
        }
        __syncthreads();

#pragma unroll
        for (int k4 = 0; k4 < KCHUNK / 4; k4++) {
            ulonglong2 wv0 = Ws2[(k4 * 4 + 0) * 32 + lane];
            ulonglong2 wv1 = Ws2[(k4 * 4 + 1) * 32 + lane];
            ulonglong2 wv2 = Ws2[(k4 * 4 + 2) * 32 + lane];
            ulonglong2 wv3 = Ws2[(k4 * 4 + 3) * 32 + lane];
#pragma unroll
            for (int i = 0; i < 8; i++) {
                const float4 xv =
                    *(const float4*)&Xs[(warp + 8 * i) * D + kc * KCHUNK + k4 * 4];
                u64 xx0 = pack2(xv.x, xv.x);
                u64 xx1 = pack2(xv.y, xv.y);
                u64 xx2 = pack2(xv.z, xv.z);
                u64 xx3 = pack2(xv.w, xv.w);
                fma2(acc[i][0], xx0, wv0.x);  fma2(acc[i][1], xx0, wv0.y);
                fma2(acc[i][0], xx1, wv1.x);  fma2(acc[i][1], xx1, wv1.y);
                fma2(acc[i][0], xx2, wv2.x);  fma2(acc[i][1], xx2, wv2.y);
                fma2(acc[i][0], xx3, wv3.x);  fma2(acc[i][1], xx3, wv3.y);
            }
        }
    }

#pragma unroll
    for (int i = 0; i < 8; i++) {
        int r = block_row + warp + 8 * i;
        if (r >= N) continue;
        float s = rsqrtf((float)(g_cnt[r] + 1));
        float4 a;
        unpack2(a.x, a.y, acc[i][0]);
        unpack2(a.z, a.w, acc[i][1]);

        __half2 h0 = __floats2half2_rn(a.x * s, a.y * s);
        __half2 h1 = __floats2half2_rn(a.z * s, a.w * s);
        float2 packed;
        packed.x = __uint_as_float(*(unsigned*)&h0);
        packed.y = __uint_as_float(*(unsigned*)&h1);
        ((float2*)(g_y + (size_t)r * D))[lane] = packed;
    }
}

// helper: accumulate one fp16 message row into fp32 acc
__device__ __forceinline__ void acc_row(float4& acc, int r, int lane) {
    float2 raw = __ldg((const float2*)(g_y + (size_t)r * D) + lane);
    unsigned u0 = __float_as_uint(raw.x);
    unsigned u1 = __float_as_uint(raw.y);
    float2 f0 = __half22float2(*(__half2*)&u0);
    float2 f1 = __half22float2(*(__half2*)&u1);
    acc.x += f0.x; acc.y += f0.y; acc.z += f1.x; acc.w += f1.y;
}

// 4) per-destination accumulate: one warp per node.
//    out[c] = bias + dinv_c * (sum_r y[r] + y[c])   -- out is WRITE-ONLY.
//    (y[c] carries the self-loop term: dinv_c * y[c] = dinv_c^2 * xw[c].)
__global__ void k_acc(const float* __restrict__ bias,
                      float* __restrict__ out, int N) {
    int lane = threadIdx.x & 31;
    int c = (blockIdx.x * blockDim.x + threadIdx.x) >> 5;
    if (c >= N) return;

    int cnt_full = g_cnt[c];
    int cnt = cnt_full > CAP ? CAP : cnt_full;   // spill handled by k_spill

    float4 acc = make_float4(0.f, 0.f, 0.f, 0.f);
    acc_row(acc, c, lane);                        // self-loop message

    const int* base = g_bucket + (size_t)c * CAP;
    for (int b = 0; b < cnt; b += 32) {
        int m = cnt - b; if (m > 32) m = 32;
        int ids = __ldg(base + b + lane);   // coalesced 128B; garbage past m OK
        int j = 0;
        for (; j + 4 <= m; j += 4) {        // 4 independent gathers in flight
            int r0 = __shfl_sync(0xffffffffu, ids, j + 0);
            int r1 = __shfl_sync(0xffffffffu, ids, j + 1);
            int r2 = __shfl_sync(0xffffffffu, ids, j + 2);
            int r3 = __shfl_sync(0xffffffffu, ids, j + 3);
            acc_row(acc, r0, lane);
            acc_row(acc, r1, lane);
            acc_row(acc, r2, lane);
            acc_row(acc, r3, lane);
        }
        for (; j < m; j++) {
            int r0 = __shfl_sync(0xffffffffu, ids, j);
            acc_row(acc, r0, lane);
        }
    }

    float s = rsqrtf((float)(cnt_full + 1));
    float4 bv = __ldg((const float4*)bias + lane);
    ((float4*)(out + (size_t)c * D))[lane] =
        make_float4(fmaf(s, acc.x, bv.x), fmaf(s, acc.y, bv.y),
                    fmaf(s, acc.z, bv.z), fmaf(s, acc.w, bv.w));
}

// 5) spill edges (expected 0): warp per edge, atomic vector RED.
//    Runs AFTER k_acc (out fully written) so the atomics are safe.
__global__ void k_spill(float* __restrict__ out, int N) {
    int lane = threadIdx.x & 31;
    int gw = (blockIdx.x * blockDim.x + threadIdx.x) >> 5;
    int nw = (gridDim.x * blockDim.x) >> 5;
    int ovf = g_ovf_cnt;
    if (ovf > OVF_MAX) ovf = OVF_MAX;
    for (int o = gw; o < ovf; o += nw) {
        int2 e = g_ovf[o];
        float norm = rsqrtf((float)(g_cnt[e.y] + 1));  // g_y already has dinv[r]
        float2 raw = __ldg((const float2*)(g_y + (size_t)e.x * D) + lane);
        unsigned u0 = __float_as_uint(raw.x);
        unsigned u1 = __float_as_uint(raw.y);
        float2 f0 = __half22float2(*(__half2*)&u0);
        float2 f1 = __half22float2(*(__half2*)&u1);
        float4 m = make_float4(f0.x * norm, f0.y * norm, f1.x * norm, f1.y * norm);
        atomicAdd((float4*)(out + (size_t)e.y * D) + lane, m);
    }
}

extern "C" void kernel_launch(void* const* d_in, const int* in_sizes, int n_in,
                              void* d_out, int out_size) {
    const float* x    = (const float*)d_in[0];
    const int*   ei   = (const int*)d_in[1];     // int32 edge_index [2, E]
    const float* w    = (const float*)d_in[2];
    const float* bias = (const float*)d_in[3];
    float*       out  = (float*)d_out;

    int N = in_sizes[0] / D;
    int E = in_sizes[1] / 2;
    const int* row = ei;
    const int* col = ei + E;

    k_zero<<<(N + 255) / 256, 256>>>(N);
    k_fill<<<(E + 255) / 256, 256>>>(row, col, E, N);
    k_gemm<<<(N + TILE_M - 1) / TILE_M, 256>>>(x, w, N);
    k_acc<<<(N * 32 + 255) / 256, 256>>>(bias, out, N);
    k_spill<<<64, 256>>>(out, N);
}

// round 8
// speedup vs baseline: 3.2082x; 1.5621x over previous
#include <cuda_runtime.h>
#include <cuda_fp16.h>

// Problem constants (fixed by the dataset)
#define MAX_N 100000
#define D 128            // D_IN == D_OUT == 128
#define ROWS_PER_BLK 64
#define CAP 64           // padded-CSR bucket capacity per node
#define OVF_MAX 65536    // overflow list capacity (expected use: 0)

// Scratch (device globals — no dynamic allocation allowed)
__device__ __align__(16) __half g_y[(size_t)MAX_N * D];  // dinv[r]*(X@W)[r], fp16
__device__ __align__(16) __half g_wt[D * D];             // W transposed [n][k], fp16
__device__ int    g_cnt[MAX_N];                    // in-degree / fill cursor
__device__ int    g_bucket[(size_t)MAX_N * CAP];   // source ids, grouped by dest
__device__ int    g_ovf_cnt;
__device__ int2   g_ovf[OVF_MAX];                  // (r, c) spill edges

// ---------------------------------------------------------------------------
// 0) one-time W transpose + fp16 convert: g_wt[n][k] = (half) W[k][n]
__global__ void k_prep(const float* __restrict__ w) {
    int idx = blockIdx.x * blockDim.x + threadIdx.x;   // 8192 threads
    if (idx >= D * D / 2) return;
    int kk = idx & 63;            // k-pair index (k = 2*kk)
    int n  = idx >> 6;
    float w0 = w[(2 * kk + 0) * D + n];
    float w1 = w[(2 * kk + 1) * D + n];
    __half2 h = __floats2half2_rn(w0, w1);
    *(__half2*)(g_wt + n * D + 2 * kk) = h;
}

// 1) zero cursors + overflow counter
__global__ void k_zero(int N) {
    int i = blockIdx.x * blockDim.x + threadIdx.x;
    if (i < N) g_cnt[i] = 0;
    if (i == 0) g_ovf_cnt = 0;
}

// 2) build padded CSR: cursor atomicAdd gives degree AND slot in one pass
__global__ void k_fill(const int* __restrict__ row,
                       const int* __restrict__ col, int E, int N) {
    int e = blockIdx.x * blockDim.x + threadIdx.x;
    if (e >= E) return;
    int r = row[e];
    int c = col[e];
    if (r == c) return;                                   // self-loop weight 0
    if ((unsigned)r >= (unsigned)N || (unsigned)c >= (unsigned)N) return;
    int slot = atomicAdd(&g_cnt[c], 1);
    if (slot < CAP) {
        g_bucket[(size_t)c * CAP + slot] = r;
    } else {
        int o = atomicAdd(&g_ovf_cnt, 1);
        if (o < OVF_MAX) g_ovf[o] = make_int2(r, c);
    }
}

// ---------------------------------------------------------------------------
// 3) Tensor-core GEMM (mma.sync m16n8k16 fp16 -> fp32):
//    g_y[r] = (half) dinv[r] * (X@W)[r]
//    Block: 128 threads = 4 warps; 64 rows x 128 cols per block.
//    Smem: Xs 64x128 fp16 (16KB) + Wt 128x128 fp16 (32KB) = 48KB, both
//    XOR-swizzled at 16B granularity (byte ^ ((row&7)<<4)) -> conflict-free.
//    Each warp: 16 rows x 128 cols, acc[16 ntiles][4] fp32.
__device__ __forceinline__ void mma16816(float* d, unsigned a0, unsigned a1,
                                         unsigned a2, unsigned a3,
                                         unsigned b0, unsigned b1) {
    asm volatile(
        "mma.sync.aligned.m16n8k16.row.col.f32.f16.f16.f32 "
        "{%0,%1,%2,%3}, {%4,%5,%6,%7}, {%8,%9}, {%0,%1,%2,%3};"
        : "+f"(d[0]), "+f"(d[1]), "+f"(d[2]), "+f"(d[3])
        : "r"(a0), "r"(a1), "r"(a2), "r"(a3), "r"(b0), "r"(b1));
}

__global__ void k_gemm(const float* __restrict__ x, int N) {
    __shared__ __align__(16) unsigned char sm[49152];
    // Xs: bytes [0, 16384): 64 rows x 256B   (row = local row)
    // Wt: bytes [16384, 49152): 128 rows x 256B (row = n)

    int tid = threadIdx.x;
    int lane = tid & 31;
    int w = tid >> 5;
    int block_row = blockIdx.x * ROWS_PER_BLK;

    // stage Wt (fp16, already transposed): 2048 x 16B chunks
    const uint4* wt4 = (const uint4*)g_wt;
#pragma unroll
    for (int i = 0; i < 16; i++) {
        int idx = tid + 128 * i;            // idx = n*16 + c
        int n = idx >> 4, c = idx & 15;
        uint4 v = wt4[idx];
        *(uint4*)(sm + 16384 + n * 256 + ((c ^ (n & 7)) << 4)) = v;
    }

    // stage Xs: load fp32, convert to fp16, swizzled 8B stores
    const float4* x4 = (const float4*)x;
#pragma unroll
    for (int i = 0; i < 16; i++) {
        int idx = tid + 128 * i;            // idx = r*32 + q
        int r = idx >> 5, q = idx & 31;     // k0 = q*4
        int gr = block_row + r;
        float4 v = make_float4(0.f, 0.f, 0.f, 0.f);
        if (gr < N) v = x4[(size_t)gr * 32 + q];
        __half2 h0 = __floats2half2_rn(v.x, v.y);
        __half2 h1 = __floats2half2_rn(v.z, v.w);
        uint2 p;
        p.x = *(unsigned*)&h0;
        p.y = *(unsigned*)&h1;
        int byte = r * 256 + q * 8;
        *(uint2*)(sm + (byte ^ ((r & 7) << 4))) = p;
    }
    __syncthreads();

    int g  = lane >> 2;        // 0..7
    int t4 = lane & 3;         // 0..3
    int swz = g << 4;          // row&7 == g for both A rows and B rows (n&7==g)

    float acc[16][4];
#pragma unroll
    for (int nt = 0; nt < 16; nt++)
#pragma unroll
        for (int j = 0; j < 4; j++) acc[nt][j] = 0.f;

    const unsigned char* xrow0 = sm + (w * 16 + g) * 256;       // local row g
    const unsigned char* xrow8 = xrow0 + 8 * 256;               // local row g+8
    const unsigned char* wbase = sm + 16384 + g * 256;          // n = nt*8 + g

#pragma unroll
    for (int ks = 0; ks < 8; ks++) {
        int kb = ks * 32 + t4 * 4;          // byte offset of k=(ks*16+t4*2)
        unsigned a0 = *(const unsigned*)(xrow0 + ( kb       ^ swz));
        unsigned a1 = *(const unsigned*)(xrow8 + ( kb       ^ swz));
        unsigned a2 = *(const unsigned*)(xrow0 + ((kb + 16) ^ swz));
        unsigned a3 = *(const unsigned*)(xrow8 + ((kb + 16) ^ swz));
#pragma unroll
        for (int nt = 0; nt < 16; nt++) {
            const unsigned char* wp = wbase + nt * 8 * 256;
            unsigned b0 = *(const unsigned*)(wp + ( kb       ^ swz));
            unsigned b1 = *(const unsigned*)(wp + ((kb + 16) ^ swz));
            mma16816(acc[nt], a0, a1, a2, a3, b0, b1);
        }
    }

    // epilogue: y = (half)(dinv * acc); rows r0 = base+g, r1 = r0+8
    int r0 = block_row + w * 16 + g;
    int r1 = r0 + 8;
    float s0 = 0.f, s1 = 0.f;
    if (r0 < N) s0 = rsqrtf((float)(g_cnt[r0] + 1));
    if (r1 < N) s1 = rsqrtf((float)(g_cnt[r1] + 1));

#pragma unroll
    for (int nt = 0; nt < 16; nt++) {
        int col = nt * 8 + t4 * 2;
        if (r0 < N) {
            __half2 h = __floats2half2_rn(acc[nt][0] * s0, acc[nt][1] * s0);
            *(__half2*)(g_y + (size_t)r0 * D + col) = h;
        }
        if (r1 < N) {
            __half2 h = __floats2half2_rn(acc[nt][2] * s1, acc[nt][3] * s1);
            *(__half2*)(g_y + (size_t)r1 * D + col) = h;
        }
    }
}

// ---------------------------------------------------------------------------
// helper: accumulate one fp16 message row into fp32 acc
__device__ __forceinline__ void acc_row(float4& acc, int r, int lane) {
    float2 raw = __ldg((const float2*)(g_y + (size_t)r * D) + lane);
    unsigned u0 = __float_as_uint(raw.x);
    unsigned u1 = __float_as_uint(raw.y);
    float2 f0 = __half22float2(*(__half2*)&u0);
    float2 f1 = __half22float2(*(__half2*)&u1);
    acc.x += f0.x; acc.y += f0.y; acc.z += f1.x; acc.w += f1.y;
}

// 4) per-destination accumulate: one warp per node.
//    out[c] = bias + dinv_c * (sum_r y[r] + y[c])   -- out is WRITE-ONLY.
__global__ void k_acc(const float* __restrict__ bias,
                      float* __restrict__ out, int N) {
    int lane = threadIdx.x & 31;
    int c = (blockIdx.x * blockDim.x + threadIdx.x) >> 5;
    if (c >= N) return;

    int cnt_full = g_cnt[c];
    int cnt = cnt_full > CAP ? CAP : cnt_full;   // spill handled by k_spill

    float4 acc = make_float4(0.f, 0.f, 0.f, 0.f);
    acc_row(acc, c, lane);                        // self-loop message

    const int* base = g_bucket + (size_t)c * CAP;
    for (int b = 0; b < cnt; b += 32) {
        int m = cnt - b; if (m > 32) m = 32;
        int ids = __ldg(base + b + lane);   // coalesced 128B; garbage past m OK
        int j = 0;
        for (; j + 4 <= m; j += 4) {        // 4 independent gathers in flight
            int r0 = __shfl_sync(0xffffffffu, ids, j + 0);
            int r1 = __shfl_sync(0xffffffffu, ids, j + 1);
            int r2 = __shfl_sync(0xffffffffu, ids, j + 2);
            int r3 = __shfl_sync(0xffffffffu, ids, j + 3);
            acc_row(acc, r0, lane);
            acc_row(acc, r1, lane);
            acc_row(acc, r2, lane);
            acc_row(acc, r3, lane);
        }
        for (; j < m; j++) {
            int r0 = __shfl_sync(0xffffffffu, ids, j);
            acc_row(acc, r0, lane);
        }
    }

    float s = rsqrtf((float)(cnt_full + 1));
    float4 bv = __ldg((const float4*)bias + lane);
    ((float4*)(out + (size_t)c * D))[lane] =
        make_float4(fmaf(s, acc.x, bv.x), fmaf(s, acc.y, bv.y),
                    fmaf(s, acc.z, bv.z), fmaf(s, acc.w, bv.w));
}

// 5) spill edges (expected 0): warp per edge, atomic vector RED.
__global__ void k_spill(float* __restrict__ out, int N) {
    int lane = threadIdx.x & 31;
    int gw = (blockIdx.x * blockDim.x + threadIdx.x) >> 5;
    int nw = (gridDim.x * blockDim.x) >> 5;
    int ovf = g_ovf_cnt;
    if (ovf > OVF_MAX) ovf = OVF_MAX;
    for (int o = gw; o < ovf; o += nw) {
        int2 e = g_ovf[o];
        float norm = rsqrtf((float)(g_cnt[e.y] + 1));  // g_y already has dinv[r]
        float2 raw = __ldg((const float2*)(g_y + (size_t)e.x * D) + lane);
        unsigned u0 = __float_as_uint(raw.x);
        unsigned u1 = __float_as_uint(raw.y);
        float2 f0 = __half22float2(*(__half2*)&u0);
        float2 f1 = __half22float2(*(__half2*)&u1);
        float4 m = make_float4(f0.x * norm, f0.y * norm, f1.x * norm, f1.y * norm);
        atomicAdd((float4*)(out + (size_t)e.y * D) + lane, m);
    }
}

extern "C" void kernel_launch(void* const* d_in, const int* in_sizes, int n_in,
                              void* d_out, int out_size) {
    const float* x    = (const float*)d_in[0];
    const int*   ei   = (const int*)d_in[1];     // int32 edge_index [2, E]
    const float* w    = (const float*)d_in[2];
    const float* bias = (const float*)d_in[3];
    float*       out  = (float*)d_out;

    int N = in_sizes[0] / D;
    int E = in_sizes[1] / 2;
    const int* row = ei;
    const int* col = ei + E;

    k_prep<<<32, 256>>>(w);
    k_zero<<<(N + 255) / 256, 256>>>(N);
    k_fill<<<(E + 255) / 256, 256>>>(row, col, E, N);
    k_gemm<<<(N + ROWS_PER_BLK - 1) / ROWS_PER_BLK, 128>>>(x, N);
    k_acc<<<(N * 32 + 255) / 256, 256>>>(bias, out, N);
    k_spill<<<64, 256>>>(out, N);
}